// round 5
// baseline (speedup 1.0000x reference)
#include <cuda_runtime.h>

#define N_NODES 4096
#define E_EDGES 131072
#define ET (E_EDGES + N_NODES)
#define NEG_SLOPE 0.2f
#define NB 148
#define NT 256
#define GSTRIDE (NB * NT)

// ---------------- scratch (device globals; no allocations) ----------------
__device__ float4 g_z4[N_NODES];              // z features (padded to 4)
__device__ float  g_zs[N_NODES];
__device__ float  g_zd[N_NODES];
__device__ float  g_S[N_NODES];               // segment sum of w
__device__ float4 g_acc4[N_NODES];            // segment sum of w*z (atomic per comp)
__device__ float  g_xf[N_NODES];              // unnormalized exp for final softmax
__device__ unsigned long long g_pack[N_NODES];
__device__ unsigned long long g_spack;        // packed argmax of xf
__device__ float  g_sum;
__device__ float  g_p12;
__device__ unsigned g_bar_cnt;
__device__ volatile unsigned g_bar_gen;

// ---------------- self-resetting software grid barrier ----------------
// __threadfence (gpu scope) emits CCTL.IVALL on sm_103a -> L1D invalidated,
// so post-barrier LDGs see other SMs' stores/atomics from L2.
__device__ __forceinline__ void grid_bar() {
    __threadfence();
    __syncthreads();
    if (threadIdx.x == 0) {
        unsigned gen = g_bar_gen;
        unsigned t = atomicAdd(&g_bar_cnt, 1u);
        if (t == NB - 1) {
            atomicExch(&g_bar_cnt, 0u);
            __threadfence();
            g_bar_gen = gen + 1u;
        } else {
            while (g_bar_gen == gen) { __nanosleep(32); }
            __threadfence();
        }
    }
    __syncthreads();
}

// edge accumulate pass, D=3 (layers 1,2)
__device__ __forceinline__ void edge_acc3(const int* __restrict__ ei, int gid) {
    float* accp = (float*)g_acc4;
    for (int e = gid; e < ET; e += GSTRIDE) {
        int s, d;
        if (e < E_EDGES) { s = ei[e]; d = ei[E_EDGES + e]; }
        else             { s = e - E_EDGES; d = s; }
        float t = g_zs[s] + g_zd[d];
        float w = expf(t >= 0.f ? t : NEG_SLOPE * t);
        float4 z = g_z4[s];
        atomicAdd(&g_S[d], w);
        atomicAdd(accp + 4 * d + 0, w * z.x);
        atomicAdd(accp + 4 * d + 1, w * z.y);
        atomicAdd(accp + 4 * d + 2, w * z.z);
    }
}

// edge accumulate pass, D=1 (layer 3)
__device__ __forceinline__ void edge_acc1(const int* __restrict__ ei, int gid) {
    float* accp = (float*)g_acc4;
    for (int e = gid; e < ET; e += GSTRIDE) {
        int s, d;
        if (e < E_EDGES) { s = ei[e]; d = ei[E_EDGES + e]; }
        else             { s = e - E_EDGES; d = s; }
        float t = g_zs[s] + g_zd[d];
        float w = expf(t >= 0.f ? t : NEG_SLOPE * t);
        float zx = g_z4[s].x;
        atomicAdd(&g_S[d], w);
        atomicAdd(accp + 4 * d, w * zx);
    }
}

__global__ void __launch_bounds__(NT, 1) mega(
    const float* __restrict__ x,   const int* __restrict__ ei,
    const float* __restrict__ W1,  const float* __restrict__ as1,
    const float* __restrict__ ad1, const float* __restrict__ b1,
    const float* __restrict__ W2,  const float* __restrict__ as2,
    const float* __restrict__ ad2, const float* __restrict__ b2,
    const float* __restrict__ W3,  const float* __restrict__ as3,
    const float* __restrict__ ad3, const float* __restrict__ b3,
    const float* __restrict__ phi1, const float* __restrict__ phi2,
    float* __restrict__ out, int out_size)
{
    __shared__ float s_f[NT];
    __shared__ unsigned long long s_u[NT];
    __shared__ int s_next[N_NODES];   // 16 KB (chase)
    __shared__ int s_vis[N_NODES];    // 16 KB (chase)

    const int tid = threadIdx.x;
    const int gid = blockIdx.x * NT + tid;

    // ---------------- P0: layer-1 prep + init + p12 ----------------
    if (gid < N_NODES) {
        float cs = 0.f, cd = 0.f;
#pragma unroll
        for (int h = 0; h < 3; h++) { cs += W1[h] * as1[h]; cd += W1[h] * ad1[h]; }
        float xv = x[gid];
        g_z4[gid] = make_float4(xv * W1[0], xv * W1[1], xv * W1[2], 0.f);
        g_zs[gid] = xv * cs;
        g_zd[gid] = xv * cd;
        g_S[gid] = 0.f;
        g_acc4[gid] = make_float4(0.f, 0.f, 0.f, 0.f);
        g_pack[gid] = 0ull;
    }
    if (gid == 0) { g_sum = 0.f; g_spack = 0ull; }
    // p12 = dot(phi1, phi2), computed by block 0 (all blocks run reduce shape)
    {
        float lp = 0.f;
        if (blockIdx.x == 0 && tid < 128) lp = phi1[tid] * phi2[tid];
        s_f[tid] = lp; __syncthreads();
        for (int s = NT / 2; s > 0; s >>= 1) {
            if (tid < s) s_f[tid] += s_f[tid + s];
            __syncthreads();
        }
        if (blockIdx.x == 0 && tid == 0) g_p12 = s_f[0];
        __syncthreads();
    }
    grid_bar();

    // ---------------- P1: layer-1 edge pass ----------------
    edge_acc3(ei, gid);
    grid_bar();

    // ---------------- P2: finish layer1 (+relu), prep layer2 ----------------
    if (gid < N_NODES) {
        float4 a = g_acc4[gid];
        float Sv = g_S[gid] + 1e-16f;
        float h0 = fmaxf(a.x / Sv + b1[0], 0.f);
        float h1 = fmaxf(a.y / Sv + b1[1], 0.f);
        float h2 = fmaxf(a.z / Sv + b1[2], 0.f);
        float zr[3]; float zs = 0.f, zd = 0.f;
#pragma unroll
        for (int r = 0; r < 3; r++) {
            zr[r] = h0 * W2[r * 3 + 0] + h1 * W2[r * 3 + 1] + h2 * W2[r * 3 + 2];
            zs += zr[r] * as2[r];
            zd += zr[r] * ad2[r];
        }
        g_z4[gid] = make_float4(zr[0], zr[1], zr[2], 0.f);
        g_zs[gid] = zs; g_zd[gid] = zd;
        g_S[gid] = 0.f;
        g_acc4[gid] = make_float4(0.f, 0.f, 0.f, 0.f);
    }
    grid_bar();

    // ---------------- P3: layer-2 edge pass ----------------
    edge_acc3(ei, gid);
    grid_bar();

    // ---------------- P4: finish layer2 (+relu), prep layer3 ----------------
    if (gid < N_NODES) {
        float4 a = g_acc4[gid];
        float Sv = g_S[gid] + 1e-16f;
        float h0 = fmaxf(a.x / Sv + b2[0], 0.f);
        float h1 = fmaxf(a.y / Sv + b2[1], 0.f);
        float h2 = fmaxf(a.z / Sv + b2[2], 0.f);
        float z = h0 * W3[0] + h1 * W3[1] + h2 * W3[2];
        g_z4[gid] = make_float4(z, 0.f, 0.f, 0.f);
        g_zs[gid] = z * as3[0];
        g_zd[gid] = z * ad3[0];
        g_S[gid] = 0.f;
        g_acc4[gid] = make_float4(0.f, 0.f, 0.f, 0.f);
    }
    grid_bar();

    // ---------------- P5: layer-3 edge pass ----------------
    edge_acc1(ei, gid);
    grid_bar();

    // ---------------- P6: final softmax numerators + sum + argmax ----------------
    {
        float b3v = b3[0];
        float lsum = 0.f;
        unsigned long long lpk = 0ull;
        for (int i = gid; i < N_NODES; i += GSTRIDE) {
            float h3 = g_acc4[i].x / (g_S[i] + 1e-16f) + b3v;
            float ex = expf(h3);
            g_xf[i] = ex;
            lsum += ex;
            unsigned long long pk =
                ((unsigned long long)__float_as_uint(ex) << 32) |
                (unsigned long long)(0xFFFFFFFFu - (unsigned)i);
            lpk = (pk > lpk) ? pk : lpk;
        }
        s_f[tid] = lsum; s_u[tid] = lpk; __syncthreads();
        for (int s = NT / 2; s > 0; s >>= 1) {
            if (tid < s) {
                s_f[tid] += s_f[tid + s];
                if (s_u[tid + s] > s_u[tid]) s_u[tid] = s_u[tid + s];
            }
            __syncthreads();
        }
        if (tid == 0) {
            atomicAdd(&g_sum, s_f[0]);
            atomicMax(&g_spack, s_u[0]);
        }
    }
    grid_bar();

    // ---------------- P7: write xo; pack next-edge keys ----------------
    {
        float sm = g_sum;
        for (int i = gid; i < N_NODES; i += GSTRIDE)
            out[i] = g_xf[i] / sm;
        float p = g_p12;
        for (int e = gid; e < E_EDGES; e += GSTRIDE) {
            int s = ei[e];
            int d = ei[E_EDGES + e];
            unsigned bits = __float_as_uint(g_xf[d]);   // ex > 0 -> ordered
            unsigned key = (p > 0.f) ? bits : ((p < 0.f) ? ~bits : 0u);
            unsigned long long pk =
                ((unsigned long long)key << 32) |
                (unsigned long long)(0xFFFFFFFFu - (unsigned)e);
            atomicMax(&g_pack[s], pk);
        }
    }
    grid_bar();

    // ---------------- P8: pointer chase (block 0 only) ----------------
    if (blockIdx.x != 0) return;
    {
        int dst0_first = ei[E_EDGES];   // dst0[0] for degree-0 nodes
        for (int i = tid; i < N_NODES; i += NT) {
            unsigned long long pk = g_pack[i];
            int nx;
            if (pk == 0ull) nx = dst0_first;
            else {
                unsigned e = 0xFFFFFFFFu - (unsigned)(pk & 0xFFFFFFFFull);
                nx = ei[E_EDGES + e];
            }
            s_next[i] = nx;
            s_vis[i] = -1;
        }
        __syncthreads();
        if (tid == 0) {
            unsigned long long sp = g_spack;
            int s = (int)(0xFFFFFFFFu - (unsigned)(sp & 0xFFFFFFFFull));
            int k = 0;
            while (k < N_NODES) {
                int v = s_vis[s];
                if (v >= 0) {                        // cycle found
                    int L = k - v;
                    int rem = (N_NODES - k) % L;
                    for (int t2 = 0; t2 < rem; t2++) s = s_next[s];
                    break;
                }
                s_vis[s] = k;
                s = s_next[s];
                k++;
            }
            if (out_size > N_NODES) out[N_NODES] = (float)s;
        }
    }
}

// ---------------- launch ----------------
extern "C" void kernel_launch(void* const* d_in, const int* in_sizes, int n_in,
                              void* d_out, int out_size) {
    const float* x   = (const float*)d_in[0];
    const int*   ei  = (const int*)  d_in[1];
    const float* W1  = (const float*)d_in[2];
    const float* as1 = (const float*)d_in[3];
    const float* ad1 = (const float*)d_in[4];
    const float* b1  = (const float*)d_in[5];
    const float* W2  = (const float*)d_in[6];
    const float* as2 = (const float*)d_in[7];
    const float* ad2 = (const float*)d_in[8];
    const float* b2  = (const float*)d_in[9];
    const float* W3  = (const float*)d_in[10];
    const float* as3 = (const float*)d_in[11];
    const float* ad3 = (const float*)d_in[12];
    const float* b3  = (const float*)d_in[13];
    const float* phi1 = (const float*)d_in[14];
    const float* phi2 = (const float*)d_in[15];
    float* out = (float*)d_out;

    mega<<<NB, NT>>>(x, ei, W1, as1, ad1, b1, W2, as2, ad2, b2,
                     W3, as3, ad3, b3, phi1, phi2, out, out_size);
}

// round 6
// speedup vs baseline: 1.4482x; 1.4482x over previous
#include <cuda_runtime.h>

#define N_NODES 4096
#define E_EDGES 131072
#define NEG_SLOPE 0.2f
#define NB 148
#define NT 256
#define GSTRIDE (NB * NT)
#define E4 (E_EDGES / 4)

// ---------------- scratch (device globals; no allocations) ----------------
__device__ float  g_S0[N_NODES];   __device__ float4 g_A0[N_NODES];   // layer1 sums
__device__ float  g_S1[N_NODES];   __device__ float4 g_A1[N_NODES];   // layer2 sums
__device__ float  g_S2[N_NODES];   __device__ float  g_a2[N_NODES];   // layer3 sums
__device__ float  g_xf[N_NODES];              // unnormalized exp(final)
__device__ unsigned long long g_pack[N_NODES];
__device__ unsigned long long g_spack;        // packed argmax of xf
__device__ float  g_sum;
__device__ float  g_p12;
__device__ unsigned g_bar_cnt;                // monotonic, reset at kernel end

// ---------------- CG-style grid barrier (monotonic count) ----------------
__device__ __forceinline__ void grid_bar(unsigned target) {
    __syncthreads();
    if (threadIdx.x == 0) {
        asm volatile("red.release.gpu.global.add.u32 [%0], 1;"
                     :: "l"(&g_bar_cnt) : "memory");
        unsigned v;
        do {
            asm volatile("ld.relaxed.gpu.global.u32 %0, [%1];"
                         : "=r"(v) : "l"(&g_bar_cnt) : "memory");
        } while (v < target);
        asm volatile("fence.acq_rel.gpu;" ::: "memory");
    }
    __syncthreads();
}

__global__ void __launch_bounds__(NT, 1) mega(
    const float* __restrict__ x,   const int* __restrict__ ei,
    const float* __restrict__ W1,  const float* __restrict__ as1,
    const float* __restrict__ ad1, const float* __restrict__ b1,
    const float* __restrict__ W2,  const float* __restrict__ as2,
    const float* __restrict__ ad2, const float* __restrict__ b2,
    const float* __restrict__ W3,  const float* __restrict__ as3,
    const float* __restrict__ ad3, const float* __restrict__ b3,
    const float* __restrict__ phi1, const float* __restrict__ phi2,
    float* __restrict__ out, int out_size)
{
    __shared__ float s_f[NT];
    __shared__ unsigned long long s_u[NT];
    __shared__ int s_next[N_NODES];
    __shared__ int s_vis[N_NODES];

    const int tid = threadIdx.x;
    const int gid = blockIdx.x * NT + tid;

    // ================= P0: zero buffers, p12 =================
    if (gid < N_NODES) {
        g_S0[gid] = 0.f; g_A0[gid] = make_float4(0.f, 0.f, 0.f, 0.f);
        g_S1[gid] = 0.f; g_A1[gid] = make_float4(0.f, 0.f, 0.f, 0.f);
        g_S2[gid] = 0.f; g_a2[gid] = 0.f;
        g_pack[gid] = 0ull;
    }
    if (gid == 0) { g_sum = 0.f; g_spack = 0ull; }
    {
        float lp = 0.f;
        if (blockIdx.x == 0 && tid < 128) lp = phi1[tid] * phi2[tid];
        s_f[tid] = lp; __syncthreads();
        for (int s = NT / 2; s > 0; s >>= 1) {
            if (tid < s) s_f[tid] += s_f[tid + s];
            __syncthreads();
        }
        if (blockIdx.x == 0 && tid == 0) g_p12 = s_f[0];
    }
    grid_bar(1 * NB);

    // ================= P1: layer-1 edge pass (prep folded in) =================
    {
        float w10 = W1[0], w11 = W1[1], w12 = W1[2];
        float cs = w10 * as1[0] + w11 * as1[1] + w12 * as1[2];
        float cd = w10 * ad1[0] + w11 * ad1[1] + w12 * ad1[2];
        float* A0p = (float*)g_A0;
        for (int q = gid; q < E4; q += GSTRIDE) {
            int4 sv = ((const int4*)ei)[q];
            int4 dv = ((const int4*)(ei + E_EDGES))[q];
#pragma unroll
            for (int j = 0; j < 4; j++) {
                int s = (&sv.x)[j], d = (&dv.x)[j];
                float xs = x[s], xd = x[d];
                float t = xs * cs + xd * cd;
                float w = expf(t >= 0.f ? t : NEG_SLOPE * t);
                atomicAdd(&g_S0[d], w);
                float wx = w * xs;
                atomicAdd(A0p + 4 * d + 0, wx * w10);
                atomicAdd(A0p + 4 * d + 1, wx * w11);
                atomicAdd(A0p + 4 * d + 2, wx * w12);
            }
        }
        for (int i = gid; i < N_NODES; i += GSTRIDE) {   // self loops
            float xs = x[i];
            float t = xs * (cs + cd);
            float w = expf(t >= 0.f ? t : NEG_SLOPE * t);
            atomicAdd(&g_S0[i], w);
            float wx = w * xs;
            atomicAdd(A0p + 4 * i + 0, wx * w10);
            atomicAdd(A0p + 4 * i + 1, wx * w11);
            atomicAdd(A0p + 4 * i + 2, wx * w12);
        }
    }
    grid_bar(2 * NB);

    // ================= P2: layer-2 edge pass (fin1 folded in) =================
    {
        float w2[9], a2s[3], a2d[3], b1r[3];
#pragma unroll
        for (int k = 0; k < 9; k++) w2[k] = W2[k];
#pragma unroll
        for (int k = 0; k < 3; k++) { a2s[k] = as2[k]; a2d[k] = ad2[k]; b1r[k] = b1[k]; }
        float* A1p = (float*)g_A1;

        auto zvec = [&](int n, float* zr) {               // h(n) -> z2 rows
            float4 a = g_A0[n];
            float Sv = g_S0[n] + 1e-16f;
            float h0 = fmaxf(a.x / Sv + b1r[0], 0.f);
            float h1 = fmaxf(a.y / Sv + b1r[1], 0.f);
            float h2 = fmaxf(a.z / Sv + b1r[2], 0.f);
#pragma unroll
            for (int r = 0; r < 3; r++)
                zr[r] = h0 * w2[r * 3 + 0] + h1 * w2[r * 3 + 1] + h2 * w2[r * 3 + 2];
        };
        for (int q = gid; q < E4; q += GSTRIDE) {
            int4 sv = ((const int4*)ei)[q];
            int4 dv = ((const int4*)(ei + E_EDGES))[q];
#pragma unroll
            for (int j = 0; j < 4; j++) {
                int s = (&sv.x)[j], d = (&dv.x)[j];
                float zs_[3], zd_[3];
                zvec(s, zs_); zvec(d, zd_);
                float t = zs_[0] * a2s[0] + zs_[1] * a2s[1] + zs_[2] * a2s[2]
                        + zd_[0] * a2d[0] + zd_[1] * a2d[1] + zd_[2] * a2d[2];
                float w = expf(t >= 0.f ? t : NEG_SLOPE * t);
                atomicAdd(&g_S1[d], w);
                atomicAdd(A1p + 4 * d + 0, w * zs_[0]);
                atomicAdd(A1p + 4 * d + 1, w * zs_[1]);
                atomicAdd(A1p + 4 * d + 2, w * zs_[2]);
            }
        }
        for (int i = gid; i < N_NODES; i += GSTRIDE) {   // self loops
            float z_[3];
            zvec(i, z_);
            float t = z_[0] * (a2s[0] + a2d[0]) + z_[1] * (a2s[1] + a2d[1])
                    + z_[2] * (a2s[2] + a2d[2]);
            float w = expf(t >= 0.f ? t : NEG_SLOPE * t);
            atomicAdd(&g_S1[i], w);
            atomicAdd(A1p + 4 * i + 0, w * z_[0]);
            atomicAdd(A1p + 4 * i + 1, w * z_[1]);
            atomicAdd(A1p + 4 * i + 2, w * z_[2]);
        }
    }
    grid_bar(3 * NB);

    // ================= P3: layer-3 edge pass (fin2 folded in) =================
    {
        float w3[3], b2r[3];
#pragma unroll
        for (int k = 0; k < 3; k++) { w3[k] = W3[k]; b2r[k] = b2[k]; }
        float a3s = as3[0], a3d = ad3[0];

        auto zscal = [&](int n) {                         // h(n) -> z3 scalar
            float4 a = g_A1[n];
            float Sv = g_S1[n] + 1e-16f;
            float h0 = fmaxf(a.x / Sv + b2r[0], 0.f);
            float h1 = fmaxf(a.y / Sv + b2r[1], 0.f);
            float h2 = fmaxf(a.z / Sv + b2r[2], 0.f);
            return h0 * w3[0] + h1 * w3[1] + h2 * w3[2];
        };
        for (int q = gid; q < E4; q += GSTRIDE) {
            int4 sv = ((const int4*)ei)[q];
            int4 dv = ((const int4*)(ei + E_EDGES))[q];
#pragma unroll
            for (int j = 0; j < 4; j++) {
                int s = (&sv.x)[j], d = (&dv.x)[j];
                float zs_ = zscal(s), zd_ = zscal(d);
                float t = zs_ * a3s + zd_ * a3d;
                float w = expf(t >= 0.f ? t : NEG_SLOPE * t);
                atomicAdd(&g_S2[d], w);
                atomicAdd(&g_a2[d], w * zs_);
            }
        }
        for (int i = gid; i < N_NODES; i += GSTRIDE) {   // self loops
            float z_ = zscal(i);
            float t = z_ * (a3s + a3d);
            float w = expf(t >= 0.f ? t : NEG_SLOPE * t);
            atomicAdd(&g_S2[i], w);
            atomicAdd(&g_a2[i], w * z_);
        }
    }
    grid_bar(4 * NB);

    // ================= P4: softmax numerators + sum + argmax =================
    {
        float b3v = b3[0];
        float lsum = 0.f;
        unsigned long long lpk = 0ull;
        for (int i = gid; i < N_NODES; i += GSTRIDE) {
            float h3 = g_a2[i] / (g_S2[i] + 1e-16f) + b3v;
            float ex = expf(h3);
            g_xf[i] = ex;
            lsum += ex;
            unsigned long long pk =
                ((unsigned long long)__float_as_uint(ex) << 32) |
                (unsigned long long)(0xFFFFFFFFu - (unsigned)i);
            lpk = (pk > lpk) ? pk : lpk;
        }
        s_f[tid] = lsum; s_u[tid] = lpk; __syncthreads();
        for (int s = NT / 2; s > 0; s >>= 1) {
            if (tid < s) {
                s_f[tid] += s_f[tid + s];
                if (s_u[tid + s] > s_u[tid]) s_u[tid] = s_u[tid + s];
            }
            __syncthreads();
        }
        if (tid == 0) {
            atomicAdd(&g_sum, s_f[0]);
            atomicMax(&g_spack, s_u[0]);
        }
    }
    grid_bar(5 * NB);

    // ================= P5: write xo; pack next-edge keys =================
    {
        float inv = 1.f / g_sum;
        for (int i = gid; i < N_NODES; i += GSTRIDE)
            out[i] = g_xf[i] * inv;
        float p = g_p12;
        for (int q = gid; q < E4; q += GSTRIDE) {
            int4 sv = ((const int4*)ei)[q];
            int4 dv = ((const int4*)(ei + E_EDGES))[q];
#pragma unroll
            for (int j = 0; j < 4; j++) {
                int s = (&sv.x)[j], d = (&dv.x)[j];
                unsigned bits = __float_as_uint(g_xf[d]);   // ex > 0 -> ordered
                unsigned key = (p > 0.f) ? bits : ((p < 0.f) ? ~bits : 0u);
                unsigned e = 4u * (unsigned)q + (unsigned)j;
                unsigned long long pk =
                    ((unsigned long long)key << 32) |
                    (unsigned long long)(0xFFFFFFFFu - e);
                atomicMax(&g_pack[s], pk);
            }
        }
    }
    grid_bar(6 * NB);

    // ================= P6: pointer chase (block 0), reset barrier =================
    if (blockIdx.x != 0) return;
    {
        int dst0_first = ei[E_EDGES];   // dst0[0] for src-degree-0 nodes
        for (int i = tid; i < N_NODES; i += NT) {
            unsigned long long pk = g_pack[i];
            int nx;
            if (pk == 0ull) nx = dst0_first;
            else {
                unsigned e = 0xFFFFFFFFu - (unsigned)(pk & 0xFFFFFFFFull);
                nx = ei[E_EDGES + e];
            }
            s_next[i] = nx;
            s_vis[i] = -1;
        }
        __syncthreads();
        if (tid == 0) {
            unsigned long long sp = g_spack;
            int s = (int)(0xFFFFFFFFu - (unsigned)(sp & 0xFFFFFFFFull));
            int k = 0;
            while (k < N_NODES) {
                int v = s_vis[s];
                if (v >= 0) {                        // cycle found -> modular skip
                    int L = k - v;
                    int rem = (N_NODES - k) % L;
                    for (int t2 = 0; t2 < rem; t2++) s = s_next[s];
                    break;
                }
                s_vis[s] = k;
                s = s_next[s];
                k++;
            }
            if (out_size > N_NODES) out[N_NODES] = (float)s;
            g_bar_cnt = 0;                           // reset for next graph replay
        }
    }
}

// ---------------- launch ----------------
extern "C" void kernel_launch(void* const* d_in, const int* in_sizes, int n_in,
                              void* d_out, int out_size) {
    const float* x   = (const float*)d_in[0];
    const int*   ei  = (const int*)  d_in[1];
    const float* W1  = (const float*)d_in[2];
    const float* as1 = (const float*)d_in[3];
    const float* ad1 = (const float*)d_in[4];
    const float* b1  = (const float*)d_in[5];
    const float* W2  = (const float*)d_in[6];
    const float* as2 = (const float*)d_in[7];
    const float* ad2 = (const float*)d_in[8];
    const float* b2  = (const float*)d_in[9];
    const float* W3  = (const float*)d_in[10];
    const float* as3 = (const float*)d_in[11];
    const float* ad3 = (const float*)d_in[12];
    const float* b3  = (const float*)d_in[13];
    const float* phi1 = (const float*)d_in[14];
    const float* phi2 = (const float*)d_in[15];
    float* out = (float*)d_out;

    mega<<<NB, NT>>>(x, ei, W1, as1, ad1, b1, W2, as2, ad2, b2,
                     W3, as3, ad3, b3, phi1, phi2, out, out_size);
}

// round 10
// speedup vs baseline: 1.7236x; 1.1902x over previous
#include <cuda_runtime.h>

#define N_NODES 4096
#define E_EDGES 131072
#define ET (E_EDGES + N_NODES)
#define NEG_SLOPE 0.2f
#define NB 148
#define NT 1024

// ---------------- scratch (device globals; no allocations) ----------------
__device__ float  g_S0[N_NODES];   __device__ float4 g_A0[N_NODES];   // layer1 sums
__device__ float  g_S1[N_NODES];   __device__ float4 g_A1[N_NODES];   // layer2 sums
__device__ float  g_S2[N_NODES];   __device__ float  g_a2[N_NODES];   // layer3 sums
__device__ float  g_xf[N_NODES];              // unnormalized exp(final)
__device__ unsigned long long g_pack[N_NODES];
__device__ unsigned long long g_spack;        // packed argmax of xf
__device__ float  g_sum;
__device__ float  g_p12;
__device__ unsigned g_bar_cnt;                // monotonic, reset at kernel end

// ---------------- CG-style grid barrier (monotonic count) ----------------
__device__ __forceinline__ void grid_bar(unsigned target) {
    __syncthreads();
    if (threadIdx.x == 0) {
        asm volatile("red.release.gpu.global.add.u32 [%0], 1;"
                     :: "l"(&g_bar_cnt) : "memory");
        unsigned v;
        do {
            asm volatile("ld.relaxed.gpu.global.u32 %0, [%1];"
                         : "=r"(v) : "l"(&g_bar_cnt) : "memory");
        } while (v < target);
        asm volatile("fence.acq_rel.gpu;" ::: "memory");   // gpu scope -> CCTL.IVALL
    }
    __syncthreads();
}

__global__ void __launch_bounds__(NT, 1) mega(
    const float* __restrict__ x,   const int* __restrict__ ei,
    const float* __restrict__ W1,  const float* __restrict__ as1,
    const float* __restrict__ ad1, const float* __restrict__ b1,
    const float* __restrict__ W2,  const float* __restrict__ as2,
    const float* __restrict__ ad2, const float* __restrict__ b2,
    const float* __restrict__ W3,  const float* __restrict__ as3,
    const float* __restrict__ ad3, const float* __restrict__ b3,
    const float* __restrict__ phi1, const float* __restrict__ phi2,
    float* __restrict__ out, int out_size)
{
    __shared__ float s_rf[32];
    __shared__ unsigned long long s_ru[32];
    __shared__ int s_next[N_NODES];   // 16 KB (chase)
    __shared__ int s_vis[N_NODES];    // 16 KB (chase)

    const int tid = threadIdx.x;
    const int gid = blockIdx.x * NT + tid;
    const int lane = tid & 31;
    const int wrp = tid >> 5;

    // ================= P0: zero buffers, p12 =================
    if (gid < N_NODES) {
        g_S0[gid] = 0.f; g_A0[gid] = make_float4(0.f, 0.f, 0.f, 0.f);
        g_S1[gid] = 0.f; g_A1[gid] = make_float4(0.f, 0.f, 0.f, 0.f);
        g_S2[gid] = 0.f; g_a2[gid] = 0.f;
        g_pack[gid] = 0ull;
    }
    if (gid == 0) { g_sum = 0.f; g_spack = 0ull; }
    if (blockIdx.x == 0 && wrp == 0) {               // p12: warp 0 of block 0
        float lp = 0.f;
#pragma unroll
        for (int k = 0; k < 4; k++)
            lp += phi1[lane + 32 * k] * phi2[lane + 32 * k];
#pragma unroll
        for (int o = 16; o > 0; o >>= 1)
            lp += __shfl_down_sync(0xFFFFFFFFu, lp, o);
        if (lane == 0) g_p12 = lp;
    }
    grid_bar(1 * NB);

    // ================= P1: layer-1 edge pass (prep folded in) =================
    if (gid < ET) {
        float w10 = W1[0], w11 = W1[1], w12 = W1[2];
        float cs = w10 * as1[0] + w11 * as1[1] + w12 * as1[2];
        float cd = w10 * ad1[0] + w11 * ad1[1] + w12 * ad1[2];
        int s, d;
        if (gid < E_EDGES) { s = ei[gid]; d = ei[E_EDGES + gid]; }
        else               { s = gid - E_EDGES; d = s; }
        float xs = x[s], xd = x[d];
        float t = xs * cs + xd * cd;
        float w = expf(t >= 0.f ? t : NEG_SLOPE * t);
        float* A0p = (float*)g_A0;
        atomicAdd(&g_S0[d], w);
        float wx = w * xs;
        atomicAdd(A0p + 4 * d + 0, wx * w10);
        atomicAdd(A0p + 4 * d + 1, wx * w11);
        atomicAdd(A0p + 4 * d + 2, wx * w12);
    }
    grid_bar(2 * NB);

    // ================= P2: layer-2 edge pass (fin1 folded in) =================
    if (gid < ET) {
        float w2[9], a2s[3], a2d[3], b1r[3];
#pragma unroll
        for (int k = 0; k < 9; k++) w2[k] = W2[k];
#pragma unroll
        for (int k = 0; k < 3; k++) { a2s[k] = as2[k]; a2d[k] = ad2[k]; b1r[k] = b1[k]; }
        int s, d;
        if (gid < E_EDGES) { s = ei[gid]; d = ei[E_EDGES + gid]; }
        else               { s = gid - E_EDGES; d = s; }

        auto zvec = [&](int n, float* zr) {           // (acc0,S0)[n] -> z2 rows
            float4 a = g_A0[n];
            float Sv = g_S0[n] + 1e-16f;
            float h0 = fmaxf(a.x / Sv + b1r[0], 0.f);
            float h1 = fmaxf(a.y / Sv + b1r[1], 0.f);
            float h2 = fmaxf(a.z / Sv + b1r[2], 0.f);
#pragma unroll
            for (int r = 0; r < 3; r++)
                zr[r] = h0 * w2[r * 3 + 0] + h1 * w2[r * 3 + 1] + h2 * w2[r * 3 + 2];
        };
        float zs_[3], zd_[3];
        zvec(s, zs_);
        if (d == s) { zd_[0] = zs_[0]; zd_[1] = zs_[1]; zd_[2] = zs_[2]; }
        else        zvec(d, zd_);
        float t = zs_[0] * a2s[0] + zs_[1] * a2s[1] + zs_[2] * a2s[2]
                + zd_[0] * a2d[0] + zd_[1] * a2d[1] + zd_[2] * a2d[2];
        float w = expf(t >= 0.f ? t : NEG_SLOPE * t);
        float* A1p = (float*)g_A1;
        atomicAdd(&g_S1[d], w);
        atomicAdd(A1p + 4 * d + 0, w * zs_[0]);
        atomicAdd(A1p + 4 * d + 1, w * zs_[1]);
        atomicAdd(A1p + 4 * d + 2, w * zs_[2]);
    }
    grid_bar(3 * NB);

    // ================= P3: layer-3 edge pass (fin2 folded in) =================
    if (gid < ET) {
        float w3[3], b2r[3];
#pragma unroll
        for (int k = 0; k < 3; k++) { w3[k] = W3[k]; b2r[k] = b2[k]; }
        float a3s = as3[0], a3d = ad3[0];
        int s, d;
        if (gid < E_EDGES) { s = ei[gid]; d = ei[E_EDGES + gid]; }
        else               { s = gid - E_EDGES; d = s; }

        auto zscal = [&](int n) {                     // (acc1,S1)[n] -> z3 scalar
            float4 a = g_A1[n];
            float Sv = g_S1[n] + 1e-16f;
            float h0 = fmaxf(a.x / Sv + b2r[0], 0.f);
            float h1 = fmaxf(a.y / Sv + b2r[1], 0.f);
            float h2 = fmaxf(a.z / Sv + b2r[2], 0.f);
            return h0 * w3[0] + h1 * w3[1] + h2 * w3[2];
        };
        float zs_ = zscal(s);
        float zd_ = (d == s) ? zs_ : zscal(d);
        float t = zs_ * a3s + zd_ * a3d;
        float w = expf(t >= 0.f ? t : NEG_SLOPE * t);
        atomicAdd(&g_S2[d], w);
        atomicAdd(&g_a2[d], w * zs_);
    }
    grid_bar(4 * NB);

    // ============ P4: softmax numerators + sum + argmax + pack (merged) ============
    {
        float b3v = b3[0];
        // edge pack: key = bits of exp(h3[d]) (recomputed; > 0 -> bits ordered)
        if (gid < E_EDGES) {
            float p = g_p12;
            int s = ei[gid];
            int d = ei[E_EDGES + gid];
            float h3d = g_a2[d] / (g_S2[d] + 1e-16f) + b3v;
            unsigned bits = __float_as_uint(expf(h3d));
            unsigned key = (p > 0.f) ? bits : ((p < 0.f) ? ~bits : 0u);
            unsigned long long pk =
                ((unsigned long long)key << 32) |
                (unsigned long long)(0xFFFFFFFFu - (unsigned)gid);
            atomicMax(&g_pack[s], pk);
        }
        // node part: exp numerator, local sum, local argmax
        float lsum = 0.f;
        unsigned long long lpk = 0ull;
        if (gid < N_NODES) {
            float h3 = g_a2[gid] / (g_S2[gid] + 1e-16f) + b3v;
            float ex = expf(h3);
            g_xf[gid] = ex;
            lsum = ex;
            lpk = ((unsigned long long)__float_as_uint(ex) << 32) |
                  (unsigned long long)(0xFFFFFFFFu - (unsigned)gid);
        }
        // warp reduce
#pragma unroll
        for (int o = 16; o > 0; o >>= 1) {
            lsum += __shfl_down_sync(0xFFFFFFFFu, lsum, o);
            unsigned long long ov = __shfl_down_sync(0xFFFFFFFFu, lpk, o);
            lpk = (ov > lpk) ? ov : lpk;
        }
        if (lane == 0) { s_rf[wrp] = lsum; s_ru[wrp] = lpk; }
        __syncthreads();
        if (wrp == 0) {
            lsum = s_rf[lane]; lpk = s_ru[lane];
#pragma unroll
            for (int o = 16; o > 0; o >>= 1) {
                lsum += __shfl_down_sync(0xFFFFFFFFu, lsum, o);
                unsigned long long ov = __shfl_down_sync(0xFFFFFFFFu, lpk, o);
                lpk = (ov > lpk) ? ov : lpk;
            }
            if (lane == 0) {
                if (lsum != 0.f) atomicAdd(&g_sum, lsum);
                if (lpk != 0ull) atomicMax(&g_spack, lpk);
            }
        }
    }
    grid_bar(5 * NB);

    // ================= P5: write xo; chase (block 0) =================
    {
        float inv = 1.f / g_sum;
        if (gid < N_NODES) out[gid] = g_xf[gid] * inv;
    }
    if (blockIdx.x != 0) return;
    {
        int dst0_first = ei[E_EDGES];   // dst0[0] for src-degree-0 nodes
        for (int i = tid; i < N_NODES; i += NT) {
            unsigned long long pk = g_pack[i];
            int nx;
            if (pk == 0ull) nx = dst0_first;
            else {
                unsigned e = 0xFFFFFFFFu - (unsigned)(pk & 0xFFFFFFFFull);
                nx = ei[E_EDGES + e];
            }
            s_next[i] = nx;
            s_vis[i] = -1;
        }
        __syncthreads();
        if (tid == 0) {
            unsigned long long sp = g_spack;
            int s = (int)(0xFFFFFFFFu - (unsigned)(sp & 0xFFFFFFFFull));
            int k = 0;
            while (k < N_NODES) {
                int v = s_vis[s];
                if (v >= 0) {                        // cycle found -> modular skip
                    int L = k - v;
                    int rem = (N_NODES - k) % L;
                    for (int t2 = 0; t2 < rem; t2++) s = s_next[s];
                    break;
                }
                s_vis[s] = k;
                s = s_next[s];
                k++;
            }
            if (out_size > N_NODES) out[N_NODES] = (float)s;
            g_bar_cnt = 0;                           // reset for next graph replay
        }
    }
}

// ---------------- launch ----------------
extern "C" void kernel_launch(void* const* d_in, const int* in_sizes, int n_in,
                              void* d_out, int out_size) {
    const float* x   = (const float*)d_in[0];
    const int*   ei  = (const int*)  d_in[1];
    const float* W1  = (const float*)d_in[2];
    const float* as1 = (const float*)d_in[3];
    const float* ad1 = (const float*)d_in[4];
    const float* b1  = (const float*)d_in[5];
    const float* W2  = (const float*)d_in[6];
    const float* as2 = (const float*)d_in[7];
    const float* ad2 = (const float*)d_in[8];
    const float* b2  = (const float*)d_in[9];
    const float* W3  = (const float*)d_in[10];
    const float* as3 = (const float*)d_in[11];
    const float* ad3 = (const float*)d_in[12];
    const float* b3  = (const float*)d_in[13];
    const float* phi1 = (const float*)d_in[14];
    const float* phi2 = (const float*)d_in[15];
    float* out = (float*)d_out;

    mega<<<NB, NT>>>(x, ei, W1, as1, ad1, b1, W2, as2, ad2, b2,
                     W3, as3, ad3, b3, phi1, phi2, out, out_size);
}

// round 11
// speedup vs baseline: 1.7915x; 1.0394x over previous
#include <cuda_runtime.h>

#define N_NODES 4096
#define E_EDGES 131072
#define ET (E_EDGES + N_NODES)
#define NEG_SLOPE 0.2f
#define NB 148
#define NT 1024

// ---------------- scratch (device globals; zero-init at module load) ----------------
// Invariant: every buffer is zero at kernel entry; each replay re-zeroes what it
// dirties, in a phase where the buffer is dead (lifetime-overlapped zeroing).
__device__ float4 g_A0[N_NODES];   // layer1: .xyz = acc(w*z), .w = S
__device__ float4 g_A1[N_NODES];   // layer2: .xyz = acc(w*z), .w = S
__device__ float2 g_M2[N_NODES];   // layer3: .x = acc(w*z),  .y = S
__device__ float  g_xf[N_NODES];   // unnormalized exp(final)  (overwritten, no zero)
__device__ unsigned long long g_pack[N_NODES];
__device__ unsigned long long g_spack;
__device__ float  g_sum;
__device__ float  g_p12;
__device__ unsigned g_bar_cnt;     // monotonic within a run; reset via g_done protocol
__device__ unsigned g_done;

// ---------------- CG-style grid barrier (monotonic count) ----------------
__device__ __forceinline__ void grid_bar(unsigned target) {
    __syncthreads();
    if (threadIdx.x == 0) {
        asm volatile("red.release.gpu.global.add.u32 [%0], 1;"
                     :: "l"(&g_bar_cnt) : "memory");
        unsigned v;
        do {
            asm volatile("ld.relaxed.gpu.global.u32 %0, [%1];"
                         : "=r"(v) : "l"(&g_bar_cnt) : "memory");
        } while (v < target);
        asm volatile("fence.acq_rel.gpu;" ::: "memory");
    }
    __syncthreads();
}

__global__ void __launch_bounds__(NT, 1) mega(
    const float* __restrict__ x,   const int* __restrict__ ei,
    const float* __restrict__ W1,  const float* __restrict__ as1,
    const float* __restrict__ ad1, const float* __restrict__ b1,
    const float* __restrict__ W2,  const float* __restrict__ as2,
    const float* __restrict__ ad2, const float* __restrict__ b2,
    const float* __restrict__ W3,  const float* __restrict__ as3,
    const float* __restrict__ ad3, const float* __restrict__ b3,
    const float* __restrict__ phi1, const float* __restrict__ phi2,
    float* __restrict__ out, int out_size)
{
    __shared__ float s_rf[32];
    __shared__ unsigned long long s_ru[32];
    __shared__ int s_next[N_NODES];   // 16 KB (chase)
    __shared__ int s_vis[N_NODES];    // 16 KB (chase)

    const int tid = threadIdx.x;
    const int gid = blockIdx.x * NT + tid;
    const int lane = tid & 31;
    const int wrp = tid >> 5;

    // ================= P1: layer-1 edge pass + p12 + zero(pack,sum,spack) =========
    if (gid < N_NODES) g_pack[gid] = 0ull;           // accumulated in P4 (3 bars away)
    if (gid == 0) { g_sum = 0.f; g_spack = 0ull; }   // accumulated in P4
    if (blockIdx.x == 0 && wrp == 1) {               // p12 (read in P4)
        float lp = 0.f;
#pragma unroll
        for (int k = 0; k < 4; k++)
            lp += phi1[lane + 32 * k] * phi2[lane + 32 * k];
#pragma unroll
        for (int o = 16; o > 0; o >>= 1)
            lp += __shfl_down_sync(0xFFFFFFFFu, lp, o);
        if (lane == 0) g_p12 = lp;
    }
    if (gid < ET) {
        float w10 = W1[0], w11 = W1[1], w12 = W1[2];
        float cs = w10 * as1[0] + w11 * as1[1] + w12 * as1[2];
        float cd = w10 * ad1[0] + w11 * ad1[1] + w12 * ad1[2];
        int s, d;
        if (gid < E_EDGES) { s = ei[gid]; d = ei[E_EDGES + gid]; }
        else               { s = gid - E_EDGES; d = s; }
        float xs = x[s], xd = x[d];
        float t = xs * cs + xd * cd;
        float w = expf(t >= 0.f ? t : NEG_SLOPE * t);
        float* A0p = (float*)g_A0;
        float wx = w * xs;
        atomicAdd(A0p + 4 * d + 0, wx * w10);
        atomicAdd(A0p + 4 * d + 1, wx * w11);
        atomicAdd(A0p + 4 * d + 2, wx * w12);
        atomicAdd(A0p + 4 * d + 3, w);               // S0 in .w
    }
    grid_bar(1 * NB);

    // ================= P2: layer-2 edge pass (fin1 folded) =================
    if (gid < ET) {
        float w2[9], a2s[3], a2d[3], b1r[3];
#pragma unroll
        for (int k = 0; k < 9; k++) w2[k] = W2[k];
#pragma unroll
        for (int k = 0; k < 3; k++) { a2s[k] = as2[k]; a2d[k] = ad2[k]; b1r[k] = b1[k]; }
        int s, d;
        if (gid < E_EDGES) { s = ei[gid]; d = ei[E_EDGES + gid]; }
        else               { s = gid - E_EDGES; d = s; }

        auto zvec = [&](int n, float* zr) {           // A0[n] -> z2 rows (1 sector)
            float4 a = g_A0[n];
            float Sv = a.w + 1e-16f;
            float h0 = fmaxf(a.x / Sv + b1r[0], 0.f);
            float h1 = fmaxf(a.y / Sv + b1r[1], 0.f);
            float h2 = fmaxf(a.z / Sv + b1r[2], 0.f);
#pragma unroll
            for (int r = 0; r < 3; r++)
                zr[r] = h0 * w2[r * 3 + 0] + h1 * w2[r * 3 + 1] + h2 * w2[r * 3 + 2];
        };
        float zs_[3], zd_[3];
        zvec(s, zs_);
        if (d == s) { zd_[0] = zs_[0]; zd_[1] = zs_[1]; zd_[2] = zs_[2]; }
        else        zvec(d, zd_);
        float t = zs_[0] * a2s[0] + zs_[1] * a2s[1] + zs_[2] * a2s[2]
                + zd_[0] * a2d[0] + zd_[1] * a2d[1] + zd_[2] * a2d[2];
        float w = expf(t >= 0.f ? t : NEG_SLOPE * t);
        float* A1p = (float*)g_A1;
        atomicAdd(A1p + 4 * d + 0, w * zs_[0]);
        atomicAdd(A1p + 4 * d + 1, w * zs_[1]);
        atomicAdd(A1p + 4 * d + 2, w * zs_[2]);
        atomicAdd(A1p + 4 * d + 3, w);               // S1 in .w
    }
    grid_bar(2 * NB);

    // ================= P3: layer-3 edge pass (fin2 folded) + zero A0 =========
    if (gid < N_NODES) g_A0[gid] = make_float4(0.f, 0.f, 0.f, 0.f);  // for next replay
    if (gid < ET) {
        float w3[3], b2r[3];
#pragma unroll
        for (int k = 0; k < 3; k++) { w3[k] = W3[k]; b2r[k] = b2[k]; }
        float a3s = as3[0], a3d = ad3[0];
        int s, d;
        if (gid < E_EDGES) { s = ei[gid]; d = ei[E_EDGES + gid]; }
        else               { s = gid - E_EDGES; d = s; }

        auto zscal = [&](int n) {                     // A1[n] -> z3 scalar (1 sector)
            float4 a = g_A1[n];
            float Sv = a.w + 1e-16f;
            float h0 = fmaxf(a.x / Sv + b2r[0], 0.f);
            float h1 = fmaxf(a.y / Sv + b2r[1], 0.f);
            float h2 = fmaxf(a.z / Sv + b2r[2], 0.f);
            return h0 * w3[0] + h1 * w3[1] + h2 * w3[2];
        };
        float zs_ = zscal(s);
        float zd_ = (d == s) ? zs_ : zscal(d);
        float t = zs_ * a3s + zd_ * a3d;
        float w = expf(t >= 0.f ? t : NEG_SLOPE * t);
        float* M2p = (float*)g_M2;
        atomicAdd(M2p + 2 * d + 0, w * zs_);
        atomicAdd(M2p + 2 * d + 1, w);               // S2 in .y
    }
    grid_bar(3 * NB);

    // ====== P4: softmax numerators + sum + argmax + edge pack + zero A1 ======
    {
        float b3v = b3[0];
        if (gid < N_NODES) g_A1[gid] = make_float4(0.f, 0.f, 0.f, 0.f);  // next replay
        // edge pack: key = bits of exp(h3[d]) (> 0 -> bits ordered)
        if (gid < E_EDGES) {
            float p = g_p12;
            int s = ei[gid];
            int d = ei[E_EDGES + gid];
            float2 m = g_M2[d];                      // 1 scattered sector
            float h3d = m.x / (m.y + 1e-16f) + b3v;
            unsigned bits = __float_as_uint(expf(h3d));
            unsigned key = (p > 0.f) ? bits : ((p < 0.f) ? ~bits : 0u);
            unsigned long long pk =
                ((unsigned long long)key << 32) |
                (unsigned long long)(0xFFFFFFFFu - (unsigned)gid);
            atomicMax(&g_pack[s], pk);
        }
        // node part: exp numerator, local sum, local argmax
        float lsum = 0.f;
        unsigned long long lpk = 0ull;
        if (gid < N_NODES) {
            float2 m = g_M2[gid];
            float h3 = m.x / (m.y + 1e-16f) + b3v;
            float ex = expf(h3);
            g_xf[gid] = ex;
            lsum = ex;
            lpk = ((unsigned long long)__float_as_uint(ex) << 32) |
                  (unsigned long long)(0xFFFFFFFFu - (unsigned)gid);
        }
#pragma unroll
        for (int o = 16; o > 0; o >>= 1) {
            lsum += __shfl_down_sync(0xFFFFFFFFu, lsum, o);
            unsigned long long ov = __shfl_down_sync(0xFFFFFFFFu, lpk, o);
            lpk = (ov > lpk) ? ov : lpk;
        }
        if (lane == 0) { s_rf[wrp] = lsum; s_ru[wrp] = lpk; }
        __syncthreads();
        if (wrp == 0) {
            lsum = s_rf[lane]; lpk = s_ru[lane];
#pragma unroll
            for (int o = 16; o > 0; o >>= 1) {
                lsum += __shfl_down_sync(0xFFFFFFFFu, lsum, o);
                unsigned long long ov = __shfl_down_sync(0xFFFFFFFFu, lpk, o);
                lpk = (ov > lpk) ? ov : lpk;
            }
            if (lane == 0) {
                if (lsum != 0.f) atomicAdd(&g_sum, lsum);
                if (lpk != 0ull) atomicMax(&g_spack, lpk);
            }
        }
    }
    grid_bar(4 * NB);

    // ================= P5: write xo + zero M2; chase (block 0); reset =========
    if (gid < N_NODES) {
        float inv = 1.f / g_sum;
        out[gid] = g_xf[gid] * inv;
        g_M2[gid] = make_float2(0.f, 0.f);           // for next replay
    }
    if (blockIdx.x != 0) {
        // final arrival: this block will never poll g_bar_cnt again
        __syncthreads();
        if (tid == 0)
            asm volatile("red.release.gpu.global.add.u32 [%0], 1;"
                         :: "l"(&g_done) : "memory");
        return;
    }
    {
        int dst0_first = ei[E_EDGES];   // dst0[0] for src-degree-0 nodes
        for (int i = tid; i < N_NODES; i += NT) {
            unsigned long long pk = g_pack[i];
            int nx;
            if (pk == 0ull) nx = dst0_first;
            else {
                unsigned e = 0xFFFFFFFFu - (unsigned)(pk & 0xFFFFFFFFull);
                nx = ei[E_EDGES + e];
            }
            s_next[i] = nx;
            s_vis[i] = -1;
        }
        __syncthreads();
        if (tid == 0) {
            unsigned long long sp = g_spack;
            int s = (int)(0xFFFFFFFFu - (unsigned)(sp & 0xFFFFFFFFull));
            int k = 0;
            while (k < N_NODES) {
                int v = s_vis[s];
                if (v >= 0) {                        // cycle -> modular skip
                    int L = k - v;
                    int rem = (N_NODES - k) % L;
                    for (int t2 = 0; t2 < rem; t2++) s = s_next[s];
                    break;
                }
                s_vis[s] = k;
                s = s_next[s];
                k++;
            }
            if (out_size > N_NODES) out[N_NODES] = (float)s;
            // race-free reset: wait until all other blocks are past their last poll
            unsigned v;
            do {
                asm volatile("ld.relaxed.gpu.global.u32 %0, [%1];"
                             : "=r"(v) : "l"(&g_done) : "memory");
            } while (v < NB - 1);
            g_bar_cnt = 0;
            g_done = 0;
        }
    }
}

// ---------------- launch ----------------
extern "C" void kernel_launch(void* const* d_in, const int* in_sizes, int n_in,
                              void* d_out, int out_size) {
    const float* x   = (const float*)d_in[0];
    const int*   ei  = (const int*)  d_in[1];
    const float* W1  = (const float*)d_in[2];
    const float* as1 = (const float*)d_in[3];
    const float* ad1 = (const float*)d_in[4];
    const float* b1  = (const float*)d_in[5];
    const float* W2  = (const float*)d_in[6];
    const float* as2 = (const float*)d_in[7];
    const float* ad2 = (const float*)d_in[8];
    const float* b2  = (const float*)d_in[9];
    const float* W3  = (const float*)d_in[10];
    const float* as3 = (const float*)d_in[11];
    const float* ad3 = (const float*)d_in[12];
    const float* b3  = (const float*)d_in[13];
    const float* phi1 = (const float*)d_in[14];
    const float* phi2 = (const float*)d_in[15];
    float* out = (float*)d_out;

    mega<<<NB, NT>>>(x, ei, W1, as1, ad1, b1, W2, as2, ad2, b2,
                     W3, as3, ad3, b3, phi1, phi2, out, out_size);
}